// round 1
// baseline (speedup 1.0000x reference)
#include <cuda_runtime.h>
#include <math.h>

#define BB 2
#define LL 2048
#define DD 1024
#define HH 16
#define DKK 64
#define DFF 4096
#define MM (BB*LL)   // 4096
#define EPS 1e-5f
#define CH 32

// ---------------- scratch (static device globals; no allocation) ----------------
__device__ float g_lny [BB*LL*DD];
__device__ float g_q   [BB*LL*DD];
__device__ float g_k   [BB*LL*DD];
__device__ float g_v   [BB*LL*DD];
__device__ float g_vsuf[BB*HH*LL*DKK];
__device__ float g_attn[BB*LL*DD];
__device__ float g_y1  [BB*LL*DD];
__device__ float g_lny1[BB*LL*DD];
__device__ float g_h   [BB*LL*DFF];
__device__ float g_part[BB*256*2];
__device__ float g_stats[BB*2];   // mu, rstd per batch

// ---------------- LayerNorm over (L,D) jointly, per batch ----------------
__global__ void ln_reduce1(const float* __restrict__ x) {
    const int batch = blockIdx.y;
    const int chunk = (LL*DD)/256;          // 8192
    long base = (long)batch*LL*DD + (long)blockIdx.x*chunk;
    float s = 0.f, s2 = 0.f;
    for (int i = threadIdx.x; i < chunk; i += 256) {
        float v = x[base + i];
        s += v; s2 += v*v;
    }
    __shared__ float sh[256], sh2[256];
    sh[threadIdx.x] = s; sh2[threadIdx.x] = s2;
    __syncthreads();
    for (int o = 128; o > 0; o >>= 1) {
        if (threadIdx.x < o) { sh[threadIdx.x] += sh[threadIdx.x+o]; sh2[threadIdx.x] += sh2[threadIdx.x+o]; }
        __syncthreads();
    }
    if (threadIdx.x == 0) {
        g_part[(batch*256 + blockIdx.x)*2 + 0] = sh[0];
        g_part[(batch*256 + blockIdx.x)*2 + 1] = sh2[0];
    }
}

__global__ void ln_reduce2() {
    const int batch = blockIdx.x;
    __shared__ float sh[256], sh2[256];
    sh[threadIdx.x]  = g_part[(batch*256 + threadIdx.x)*2 + 0];
    sh2[threadIdx.x] = g_part[(batch*256 + threadIdx.x)*2 + 1];
    __syncthreads();
    for (int o = 128; o > 0; o >>= 1) {
        if (threadIdx.x < o) { sh[threadIdx.x] += sh[threadIdx.x+o]; sh2[threadIdx.x] += sh2[threadIdx.x+o]; }
        __syncthreads();
    }
    if (threadIdx.x == 0) {
        const float inv = 1.0f / (float)(LL*DD);
        float mu  = sh[0]  * inv;
        float var = sh2[0] * inv - mu*mu;
        g_stats[batch*2 + 0] = mu;
        g_stats[batch*2 + 1] = rsqrtf(var + EPS);
    }
}

__global__ void ln_apply(const float* __restrict__ x, const float* __restrict__ w,
                         const float* __restrict__ b, float* __restrict__ out) {
    const int batch = blockIdx.y;
    const float mu   = g_stats[batch*2 + 0];
    const float rstd = g_stats[batch*2 + 1];
    const long base = (long)batch*LL*DD;
    for (long i = (long)blockIdx.x*blockDim.x + threadIdx.x; i < (long)LL*DD; i += (long)gridDim.x*blockDim.x) {
        out[base + i] = (x[base + i] - mu) * rstd * w[i] + b[i];
    }
}

// ---------------- SGEMM: C[M,N] = A[M,K] @ W[K,N] + bias (+ epilogue) ----------------
// EPI: 0 = bias, 1 = bias+relu, 2 = bias+residual
template<int EPI>
__global__ void __launch_bounds__(256, 2)
sgemm_kernel(const float* __restrict__ A, const float* __restrict__ W,
             const float* __restrict__ bias, const float* __restrict__ R,
             float* __restrict__ C, int Mn, int N, int K)
{
    __shared__ float As[8][128];
    __shared__ float Bs[8][128];
    const int bm = blockIdx.y * 128;
    const int bn = blockIdx.x * 128;
    const int t  = threadIdx.x;
    const int tx = t & 15, ty = t >> 4;

    float acc[8][8];
    #pragma unroll
    for (int i = 0; i < 8; i++)
        #pragma unroll
        for (int j = 0; j < 8; j++) acc[i][j] = 0.f;

    const int arow = t >> 1, ac4 = (t & 1) * 4;
    const int brow = t >> 5, bc4 = (t & 31) * 4;
    const float* Aptr = A + (long)(bm + arow)*K + ac4;
    const float* Bptr = W + (long)brow*N + bn + bc4;

    for (int k0 = 0; k0 < K; k0 += 8) {
        float4 av = *(const float4*)(Aptr + k0);
        float4 bv = *(const float4*)(Bptr + (long)k0*N);
        As[ac4+0][arow] = av.x;
        As[ac4+1][arow] = av.y;
        As[ac4+2][arow] = av.z;
        As[ac4+3][arow] = av.w;
        *(float4*)&Bs[brow][bc4] = bv;
        __syncthreads();
        #pragma unroll
        for (int kk = 0; kk < 8; kk++) {
            float4 a0 = *(const float4*)&As[kk][ty*8];
            float4 a1 = *(const float4*)&As[kk][ty*8+4];
            float4 b0 = *(const float4*)&Bs[kk][tx*8];
            float4 b1 = *(const float4*)&Bs[kk][tx*8+4];
            float a[8] = {a0.x,a0.y,a0.z,a0.w,a1.x,a1.y,a1.z,a1.w};
            float bfr[8] = {b0.x,b0.y,b0.z,b0.w,b1.x,b1.y,b1.z,b1.w};
            #pragma unroll
            for (int i = 0; i < 8; i++)
                #pragma unroll
                for (int j = 0; j < 8; j++)
                    acc[i][j] += a[i] * bfr[j];
        }
        __syncthreads();
    }

    #pragma unroll
    for (int i = 0; i < 8; i++) {
        const int row = bm + ty*8 + i;
        #pragma unroll
        for (int j = 0; j < 8; j++) {
            const int col = bn + tx*8 + j;
            float c = acc[i][j] + bias[col];
            if (EPI == 1) c = fmaxf(c, 0.f);
            if (EPI == 2) c += R[(long)row*N + col];
            C[(long)row*N + col] = c;
        }
    }
}

// ---------------- exclusive suffix sums of V per (b,h): vsuf[q][d] = sum_{k>q} v[k][d] ----------------
__global__ void vsuffix_kernel() {
    const int bh = blockIdx.x;
    const int b = bh / HH, h = bh % HH;
    const int d = threadIdx.x;    // 64 threads
    float acc = 0.f;
    for (int k = LL - 1; k >= 0; k--) {
        g_vsuf[((long)bh*LL + k)*DKK + d] = acc;
        acc += g_v[((long)(b*LL + k))*DD + h*DKK + d];
    }
}

// ---------------- attention: tril-to-ZERO masked softmax, flash style + analytic tail ----------------
// warp w handles query row q = blockIdx.x*8 + w; only iterates k <= q; k > q handled in closed form.
__global__ void __launch_bounds__(256)
attn_kernel(float* __restrict__ out) {
    __shared__ float sQ[8][DKK];
    __shared__ float sK[CH][DKK + 1];
    __shared__ float sV[CH][DKK];

    const int b = blockIdx.z, h = blockIdx.y;
    const int q0 = blockIdx.x * 8;
    const int t = threadIdx.x, w = t >> 5, lane = t & 31;
    const int q = q0 + w;

    for (int i = t; i < 8*DKK; i += 256) {
        int r = i >> 6, d = i & 63;
        sQ[r][d] = g_q[((long)(b*LL + q0 + r))*DD + h*DKK + d];
    }

    float m = 0.f, l = 0.f, o0 = 0.f, o1 = 0.f;
    const int kmax = q0 + 7;

    for (int kc = 0; kc <= kmax; kc += CH) {
        __syncthreads();
        for (int i = t; i < CH*DKK; i += 256) {
            int r = i >> 6, d = i & 63;
            int kidx = kc + r;
            float kvK = 0.f, kvV = 0.f;
            if (kidx < LL) {
                long gi = ((long)(b*LL + kidx))*DD + h*DKK + d;
                kvK = g_k[gi]; kvV = g_v[gi];
            }
            sK[r][d] = kvK; sV[r][d] = kvV;
        }
        __syncthreads();

        const int k = kc + lane;
        const bool valid = (k <= q);
        float s = -1e30f;
        if (valid) {
            float acc = 0.f;
            #pragma unroll
            for (int d = 0; d < DKK; d++) acc += sQ[w][d] * sK[lane][d];
            s = acc * 0.125f;   // 1/sqrt(64)
        }
        float mc = s;
        #pragma unroll
        for (int off = 16; off; off >>= 1) mc = fmaxf(mc, __shfl_xor_sync(0xffffffffu, mc, off));
        const float mnew = fmaxf(m, mc);
        const float scale = __expf(m - mnew);
        const float p = valid ? __expf(s - mnew) : 0.f;
        float psum = p;
        #pragma unroll
        for (int off = 16; off; off >>= 1) psum += __shfl_xor_sync(0xffffffffu, psum, off);
        l = l * scale + psum;
        o0 *= scale; o1 *= scale;
        #pragma unroll
        for (int j = 0; j < CH; j++) {
            float pj = __shfl_sync(0xffffffffu, p, j);
            o0 += pj * sV[j][lane];
            o1 += pj * sV[j][lane + 32];
        }
        m = mnew;
    }

    // masked (k>q) entries all have score 0: contribute (L-1-q)*e^{-m} to denom, e^{-m}*Vsuf to numer
    const float e0 = __expf(-m);
    const float den = l + (float)(LL - 1 - q) * e0;
    const long vs = ((long)((b*HH + h)*LL + q))*DKK;
    const float n0 = o0 + e0 * g_vsuf[vs + lane];
    const float n1 = o1 + e0 * g_vsuf[vs + lane + 32];
    const long oi = ((long)(b*LL + q))*DD + h*DKK;
    out[oi + lane]      = n0 / den;
    out[oi + lane + 32] = n1 / den;
}

// ---------------- launch ----------------
extern "C" void kernel_launch(void* const* d_in, const int* in_sizes, int n_in,
                              void* d_out, int out_size) {
    const float* x    = (const float*)d_in[0];
    const float* y    = (const float*)d_in[1];
    const float* Wq   = (const float*)d_in[2];
    const float* bq   = (const float*)d_in[3];
    const float* Wk   = (const float*)d_in[4];
    const float* bk   = (const float*)d_in[5];
    const float* Wv   = (const float*)d_in[6];
    const float* bv   = (const float*)d_in[7];
    const float* Wo   = (const float*)d_in[8];
    const float* bo   = (const float*)d_in[9];
    const float* W1   = (const float*)d_in[10];
    const float* b1   = (const float*)d_in[11];
    const float* W2   = (const float*)d_in[12];
    const float* b2   = (const float*)d_in[13];
    const float* ln1w = (const float*)d_in[14];
    const float* ln1b = (const float*)d_in[15];
    const float* ln2w = (const float*)d_in[16];
    const float* ln2b = (const float*)d_in[17];
    float* out = (float*)d_out;

    float *p_lny, *p_q, *p_k, *p_v, *p_attn, *p_y1, *p_lny1, *p_h;
    cudaGetSymbolAddress((void**)&p_lny,  g_lny);
    cudaGetSymbolAddress((void**)&p_q,    g_q);
    cudaGetSymbolAddress((void**)&p_k,    g_k);
    cudaGetSymbolAddress((void**)&p_v,    g_v);
    cudaGetSymbolAddress((void**)&p_attn, g_attn);
    cudaGetSymbolAddress((void**)&p_y1,   g_y1);
    cudaGetSymbolAddress((void**)&p_lny1, g_lny1);
    cudaGetSymbolAddress((void**)&p_h,    g_h);

    // LN1 on y
    ln_reduce1<<<dim3(256, BB), 256>>>(y);
    ln_reduce2<<<BB, 256>>>();
    ln_apply<<<dim3(256, BB), 256>>>(y, ln1w, ln1b, p_lny);

    // Q = x@Wq+bq ; K = lny@Wk+bk ; V = lny@Wv+bv
    sgemm_kernel<0><<<dim3(DD/128, MM/128), 256>>>(x,     Wq, bq, nullptr, p_q, MM, DD, DD);
    sgemm_kernel<0><<<dim3(DD/128, MM/128), 256>>>(p_lny, Wk, bk, nullptr, p_k, MM, DD, DD);
    sgemm_kernel<0><<<dim3(DD/128, MM/128), 256>>>(p_lny, Wv, bv, nullptr, p_v, MM, DD, DD);

    // suffix sums of V, then attention
    vsuffix_kernel<<<BB*HH, DKK>>>();
    attn_kernel<<<dim3(LL/8, HH, BB), 256>>>(p_attn);

    // y1 = y + attn@Wo + bo
    sgemm_kernel<2><<<dim3(DD/128, MM/128), 256>>>(p_attn, Wo, bo, y, p_y1, MM, DD, DD);

    // LN2 on y1
    ln_reduce1<<<dim3(256, BB), 256>>>(p_y1);
    ln_reduce2<<<BB, 256>>>();
    ln_apply<<<dim3(256, BB), 256>>>(p_y1, ln2w, ln2b, p_lny1);

    // h = relu(lny1@W1 + b1) ; out = y1 + h@W2 + b2
    sgemm_kernel<1><<<dim3(DFF/128, MM/128), 256>>>(p_lny1, W1, b1, nullptr, p_h, MM, DFF, DD);
    sgemm_kernel<2><<<dim3(DD/128,  MM/128), 256>>>(p_h,    W2, b2, p_y1,    out, MM, DD, DFF);
}

// round 3
// speedup vs baseline: 1.9074x; 1.9074x over previous
#include <cuda_runtime.h>
#include <cuda_bf16.h>
#include <math.h>
#include <stdint.h>

#define BB 2
#define LL 2048
#define DD 1024
#define HH 16
#define DKK 64
#define DFF 4096
#define MM (BB*LL)   // 4096
#define EPS 1e-5f
#define CH 32
#define RPB 16       // attention rows per block

// ================= helpers =================
__device__ __forceinline__ uint32_t smem_u32(const void* p) {
    uint32_t a;
    asm("{ .reg .u64 t; cvta.to.shared.u64 t, %1; cvt.u32.u64 %0, t; }" : "=r"(a) : "l"(p));
    return a;
}

#define LDSM_X4(r, addr) \
    asm volatile("ldmatrix.sync.aligned.m8n8.x4.shared.b16 {%0,%1,%2,%3}, [%4];" \
        : "=r"((r)[0]), "=r"((r)[1]), "=r"((r)[2]), "=r"((r)[3]) : "r"(addr))
#define LDSM_X4T(r, addr) \
    asm volatile("ldmatrix.sync.aligned.m8n8.x4.trans.shared.b16 {%0,%1,%2,%3}, [%4];" \
        : "=r"((r)[0]), "=r"((r)[1]), "=r"((r)[2]), "=r"((r)[3]) : "r"(addr))

#define MMA16816(d, a, b0, b1) \
    asm volatile("mma.sync.aligned.m16n8k16.row.col.f32.bf16.bf16.f32 " \
        "{%0,%1,%2,%3}, {%4,%5,%6,%7}, {%8,%9}, {%0,%1,%2,%3};" \
        : "+f"((d)[0]), "+f"((d)[1]), "+f"((d)[2]), "+f"((d)[3]) \
        : "r"((a)[0]), "r"((a)[1]), "r"((a)[2]), "r"((a)[3]), "r"(b0), "r"(b1))

#define STS128U(addr, a, b, c, d) \
    asm volatile("st.shared.v4.b32 [%0], {%1, %2, %3, %4};" \
                 :: "r"((uint32_t)(addr)), "r"(a), "r"(b), "r"(c), "r"(d) : "memory")

// exact split: x = hi + lo, hi = truncate-to-bf16(x); pack pairs (x0 -> low half)
__device__ __forceinline__ void split2(float x0, float x1, uint32_t& hi, uint32_t& lo) {
    uint32_t u0 = __float_as_uint(x0) & 0xffff0000u;
    uint32_t u1 = __float_as_uint(x1) & 0xffff0000u;
    hi = (u0 >> 16) | u1;
    float l0 = x0 - __uint_as_float(u0);
    float l1 = x1 - __uint_as_float(u1);
    __nv_bfloat162 p = __float22bfloat162_rn(make_float2(l0, l1));
    lo = *reinterpret_cast<uint32_t*>(&p);
}

// ================= scratch =================
__device__ float g_lny [BB*LL*DD];
__device__ float g_q   [BB*LL*DD];
__device__ float g_k   [BB*LL*DD];
__device__ float g_v   [BB*LL*DD];
__device__ float g_vsuf[BB*HH*LL*DKK];
__device__ float g_attn[BB*LL*DD];
__device__ float g_y1  [BB*LL*DD];
__device__ float g_lny1[BB*LL*DD];
__device__ float g_h   [BB*LL*DFF];
__device__ float g_part[BB*256*2];
__device__ float g_stats[BB*2];

// ================= LayerNorm over (L,D) jointly =================
__global__ void ln_reduce1(const float* __restrict__ x) {
    const int batch = blockIdx.y;
    const int chunk = (LL*DD)/256;
    long base = (long)batch*LL*DD + (long)blockIdx.x*chunk;
    float s = 0.f, s2 = 0.f;
    for (int i = threadIdx.x; i < chunk; i += 256) {
        float v = x[base + i];
        s += v; s2 += v*v;
    }
    __shared__ float sh[256], sh2[256];
    sh[threadIdx.x] = s; sh2[threadIdx.x] = s2;
    __syncthreads();
    for (int o = 128; o > 0; o >>= 1) {
        if (threadIdx.x < o) { sh[threadIdx.x] += sh[threadIdx.x+o]; sh2[threadIdx.x] += sh2[threadIdx.x+o]; }
        __syncthreads();
    }
    if (threadIdx.x == 0) {
        g_part[(batch*256 + blockIdx.x)*2 + 0] = sh[0];
        g_part[(batch*256 + blockIdx.x)*2 + 1] = sh2[0];
    }
}

__global__ void ln_reduce2() {
    const int batch = blockIdx.x;
    __shared__ float sh[256], sh2[256];
    sh[threadIdx.x]  = g_part[(batch*256 + threadIdx.x)*2 + 0];
    sh2[threadIdx.x] = g_part[(batch*256 + threadIdx.x)*2 + 1];
    __syncthreads();
    for (int o = 128; o > 0; o >>= 1) {
        if (threadIdx.x < o) { sh[threadIdx.x] += sh[threadIdx.x+o]; sh2[threadIdx.x] += sh2[threadIdx.x+o]; }
        __syncthreads();
    }
    if (threadIdx.x == 0) {
        const float inv = 1.0f / (float)(LL*DD);
        float mu  = sh[0]  * inv;
        float var = sh2[0] * inv - mu*mu;
        g_stats[batch*2 + 0] = mu;
        g_stats[batch*2 + 1] = rsqrtf(var + EPS);
    }
}

__global__ void ln_apply(const float* __restrict__ x, const float* __restrict__ w,
                         const float* __restrict__ b, float* __restrict__ out) {
    const int batch = blockIdx.y;
    const float mu   = g_stats[batch*2 + 0];
    const float rstd = g_stats[batch*2 + 1];
    const long base = (long)batch*LL*DD;
    for (long i = (long)blockIdx.x*blockDim.x + threadIdx.x; i < (long)LL*DD; i += (long)gridDim.x*blockDim.x) {
        out[base + i] = (x[base + i] - mu) * rstd * w[i] + b[i];
    }
}

// ================= bf16x3 mma.sync GEMM =================
// C[M,N] = A[M,K]@W[K,N] + bias (+relu / +residual)
// CTA 256 thr, tile 128x128, k-chunk 16, double buffered.
// A smem: [128 rows][16 k] bf16, row stride 48B (hi at 0, lo at +6144)
// B smem: [16 k rows][128 n] bf16, row stride 272B (hi at 12288, lo at +4352)
#define ASTR 48
#define BSTR 272
#define OFF_ALO 6144
#define OFF_BHI 12288
#define OFF_BLO 16640
#define STAGE   20992

template<int EPI>
__global__ void __launch_bounds__(256)
tgemm(const float* __restrict__ A, const float* __restrict__ W,
      const float* __restrict__ bias, const float* __restrict__ R,
      float* __restrict__ C, int N, int K)
{
    __shared__ __align__(128) char sm[2*STAGE];
    const uint32_t sbase = smem_u32(sm);

    const int t = threadIdx.x;
    const int lane = t & 31, wid = t >> 5;
    const int g = lane >> 2, tig = lane & 3;
    const int wm = wid >> 2, wn = wid & 3;         // 2 x 4 warp grid
    const int bm = blockIdx.y * 128, bn = blockIdx.x * 128;

    // loader indices
    const int ar = t >> 1, aq = t & 1;             // A: row, k-quad (0/1 -> k 0..7 / 8..15)
    const int br = t >> 4, bc = (t & 15) * 8;      // B: k row, n col base

    const float* Agp = A + (size_t)(bm + ar) * K + aq * 8;
    const float* Bgp = W + (size_t)br * N + bn + bc;

    // ldmatrix lane addresses (within stage)
    const uint32_t a_base = sbase + (uint32_t)(wm*64 + (lane & 15)) * ASTR + ((lane >> 4) & 1) * 16;
    const uint32_t b_base = sbase + OFF_BHI + (uint32_t)(lane & 15) * BSTR + (uint32_t)wn * 64 + ((lane >> 4) & 1) * 16;

    float acc[4][4][4];
    #pragma unroll
    for (int i = 0; i < 4; i++)
        #pragma unroll
        for (int j = 0; j < 4; j++)
            #pragma unroll
            for (int c = 0; c < 4; c++) acc[i][j][c] = 0.f;

    const int nk = K / 16;

    float4 av0, av1, bv0, bv1;
    // prefetch stage 0
    av0 = *(const float4*)(Agp);
    av1 = *(const float4*)(Agp + 4);
    bv0 = *(const float4*)(Bgp);
    bv1 = *(const float4*)(Bgp + 4);

    auto store_stage = [&](int buf) {
        const uint32_t sb = sbase + (uint32_t)buf * STAGE;
        uint32_t h0,l0,h1,l1,h2,l2,h3,l3;
        split2(av0.x, av0.y, h0, l0);
        split2(av0.z, av0.w, h1, l1);
        split2(av1.x, av1.y, h2, l2);
        split2(av1.z, av1.w, h3, l3);
        uint32_t aaddr = sb + (uint32_t)ar * ASTR + (uint32_t)aq * 16;
        STS128U(aaddr, h0, h1, h2, h3);
        STS128U(aaddr + OFF_ALO, l0, l1, l2, l3);
        split2(bv0.x, bv0.y, h0, l0);
        split2(bv0.z, bv0.w, h1, l1);
        split2(bv1.x, bv1.y, h2, l2);
        split2(bv1.z, bv1.w, h3, l3);
        uint32_t baddr = sb + OFF_BHI + (uint32_t)br * BSTR + (uint32_t)bc * 2;
        STS128U(baddr, h0, h1, h2, h3);
        STS128U(baddr + (OFF_BLO - OFF_BHI), l0, l1, l2, l3);
    };

    store_stage(0);
    __syncthreads();

    for (int s = 0; s < nk; s++) {
        const int buf = s & 1;
        // prefetch next stage (gmem -> regs), overlaps the mma work below
        if (s + 1 < nk) {
            const int k0 = (s + 1) * 16;
            av0 = *(const float4*)(Agp + k0);
            av1 = *(const float4*)(Agp + k0 + 4);
            bv0 = *(const float4*)(Bgp + (size_t)k0 * N);
            bv1 = *(const float4*)(Bgp + (size_t)k0 * N + 4);
        }

        const uint32_t so = (uint32_t)buf * STAGE;
        uint32_t ah[4][4], bhf[2][4];
        #pragma unroll
        for (int i = 0; i < 4; i++) LDSM_X4(ah[i], a_base + so + i * (16*ASTR));
        #pragma unroll
        for (int j2 = 0; j2 < 2; j2++) LDSM_X4T(bhf[j2], b_base + so + j2 * 32);

        // pass 1: hi * hi
        #pragma unroll
        for (int i = 0; i < 4; i++)
            #pragma unroll
            for (int j = 0; j < 4; j++)
                MMA16816(acc[i][j], ah[i], bhf[j>>1][(j&1)*2], bhf[j>>1][(j&1)*2+1]);

        // pass 2: hi * lo
        {
            uint32_t blf[2][4];
            #pragma unroll
            for (int j2 = 0; j2 < 2; j2++) LDSM_X4T(blf[j2], b_base + so + (OFF_BLO - OFF_BHI) + j2 * 32);
            #pragma unroll
            for (int i = 0; i < 4; i++)
                #pragma unroll
                for (int j = 0; j < 4; j++)
                    MMA16816(acc[i][j], ah[i], blf[j>>1][(j&1)*2], blf[j>>1][(j&1)*2+1]);
        }
        // pass 3: lo * hi
        {
            uint32_t alf[4][4];
            #pragma unroll
            for (int i = 0; i < 4; i++) LDSM_X4(alf[i], a_base + so + OFF_ALO + i * (16*ASTR));
            #pragma unroll
            for (int i = 0; i < 4; i++)
                #pragma unroll
                for (int j = 0; j < 4; j++)
                    MMA16816(acc[i][j], alf[i], bhf[j>>1][(j&1)*2], bhf[j>>1][(j&1)*2+1]);
        }

        if (s + 1 < nk) store_stage(buf ^ 1);
        __syncthreads();
    }

    // epilogue
    #pragma unroll
    for (int i = 0; i < 4; i++) {
        const int row0 = bm + wm*64 + i*16 + g;
        #pragma unroll
        for (int j = 0; j < 4; j++) {
            const int col0 = bn + wn*32 + j*8 + 2*tig;
            float2 bs = *(const float2*)(bias + col0);
            float2 c01 = make_float2(acc[i][j][0] + bs.x, acc[i][j][1] + bs.y);
            float2 c23 = make_float2(acc[i][j][2] + bs.x, acc[i][j][3] + bs.y);
            if (EPI == 1) {
                c01.x = fmaxf(c01.x, 0.f); c01.y = fmaxf(c01.y, 0.f);
                c23.x = fmaxf(c23.x, 0.f); c23.y = fmaxf(c23.y, 0.f);
            }
            if (EPI == 2) {
                float2 r0 = *(const float2*)(R + (size_t)row0 * N + col0);
                float2 r1 = *(const float2*)(R + (size_t)(row0+8) * N + col0);
                c01.x += r0.x; c01.y += r0.y;
                c23.x += r1.x; c23.y += r1.y;
            }
            *(float2*)(C + (size_t)row0 * N + col0)     = c01;
            *(float2*)(C + (size_t)(row0+8) * N + col0) = c23;
        }
    }
}

// ================= V suffix sums (segmented scan) =================
__global__ void __launch_bounds__(1024) vsuffix_kernel() {
    const int bh = blockIdx.x;
    const int b = bh / HH, h = bh % HH;
    const int d = threadIdx.x & 63;
    const int seg = threadIdx.x >> 6;         // 0..15
    const int SEGK = LL / 16;                 // 128
    __shared__ float part[16][64];
    const size_t vbase = (size_t)b*LL*DD + (size_t)h*DKK + d;
    const int k0 = seg * SEGK;
    float s = 0.f;
    for (int k = k0; k < k0 + SEGK; k++) s += g_v[vbase + (size_t)k*DD];
    part[seg][d] = s;
    __syncthreads();
    float acc = 0.f;
    for (int ss = seg + 1; ss < 16; ss++) acc += part[ss][d];
    const size_t sb = (size_t)bh*LL*DKK + d;
    for (int k = k0 + SEGK - 1; k >= k0; k--) {
        g_vsuf[sb + (size_t)k*DKK] = acc;
        acc += g_v[vbase + (size_t)k*DD];
    }
}

// ================= attention (tril-to-zero softmax + analytic tail) =================
__global__ void __launch_bounds__(512)
attn_kernel(float* __restrict__ out) {
    __shared__ float sQ[RPB][DKK];
    __shared__ float sK[CH][DKK + 1];
    __shared__ float sV[CH][DKK];

    const int b = blockIdx.z, h = blockIdx.y;
    const int q0 = blockIdx.x * RPB;
    const int t = threadIdx.x, w = t >> 5, lane = t & 31;
    const int q = q0 + w;

    for (int i = t; i < RPB*DKK; i += 512) {
        int r = i >> 6, d = i & 63;
        sQ[r][d] = g_q[((long)(b*LL + q0 + r))*DD + h*DKK + d];
    }

    float m = 0.f, l = 0.f, o0 = 0.f, o1 = 0.f;
    const int kmax = q0 + RPB - 1;

    for (int kc = 0; kc <= kmax; kc += CH) {
        __syncthreads();
        for (int i = t; i < CH*DKK; i += 512) {
            int r = i >> 6, d = i & 63;
            int kidx = kc + r;
            long gi = ((long)(b*LL + kidx))*DD + h*DKK + d;
            sK[r][d] = g_k[gi]; sV[r][d] = g_v[gi];
        }
        __syncthreads();

        const int k = kc + lane;
        const bool valid = (k <= q);
        float s = -1e30f;
        if (valid) {
            float acc = 0.f;
            #pragma unroll
            for (int d = 0; d < DKK; d++) acc += sQ[w][d] * sK[lane][d];
            s = acc * 0.125f;
        }
        float mc = s;
        #pragma unroll
        for (int off = 16; off; off >>= 1) mc = fmaxf(mc, __shfl_xor_sync(0xffffffffu, mc, off));
        const float mnew = fmaxf(m, mc);
        const float scale = __expf(m - mnew);
        const float p = valid ? __expf(s - mnew) : 0.f;
        float psum = p;
        #pragma unroll
        for (int off = 16; off; off >>= 1) psum += __shfl_xor_sync(0xffffffffu, psum, off);
        l = l * scale + psum;
        o0 *= scale; o1 *= scale;
        #pragma unroll
        for (int j = 0; j < CH; j++) {
            float pj = __shfl_sync(0xffffffffu, p, j);
            o0 += pj * sV[j][lane];
            o1 += pj * sV[j][lane + 32];
        }
        m = mnew;
    }

    const float e0 = __expf(-m);
    const float den = l + (float)(LL - 1 - q) * e0;
    const long vs = ((long)((b*HH + h)*LL + q))*DKK;
    const float n0 = o0 + e0 * g_vsuf[vs + lane];
    const float n1 = o1 + e0 * g_vsuf[vs + lane + 32];
    const long oi = ((long)(b*LL + q))*DD + h*DKK;
    out[oi + lane]      = n0 / den;
    out[oi + lane + 32] = n1 / den;
}

// ================= launch =================
extern "C" void kernel_launch(void* const* d_in, const int* in_sizes, int n_in,
                              void* d_out, int out_size) {
    const float* x    = (const float*)d_in[0];
    const float* y    = (const float*)d_in[1];
    const float* Wq   = (const float*)d_in[2];
    const float* bq   = (const float*)d_in[3];
    const float* Wk   = (const float*)d_in[4];
    const float* bk   = (const float*)d_in[5];
    const float* Wv   = (const float*)d_in[6];
    const float* bv   = (const float*)d_in[7];
    const float* Wo   = (const float*)d_in[8];
    const float* bo   = (const float*)d_in[9];
    const float* W1   = (const float*)d_in[10];
    const float* b1   = (const float*)d_in[11];
    const float* W2   = (const float*)d_in[12];
    const float* b2   = (const float*)d_in[13];
    const float* ln1w = (const float*)d_in[14];
    const float* ln1b = (const float*)d_in[15];
    const float* ln2w = (const float*)d_in[16];
    const float* ln2b = (const float*)d_in[17];
    float* out = (float*)d_out;

    float *p_lny, *p_q, *p_k, *p_v, *p_attn, *p_y1, *p_lny1, *p_h;
    cudaGetSymbolAddress((void**)&p_lny,  g_lny);
    cudaGetSymbolAddress((void**)&p_q,    g_q);
    cudaGetSymbolAddress((void**)&p_k,    g_k);
    cudaGetSymbolAddress((void**)&p_v,    g_v);
    cudaGetSymbolAddress((void**)&p_attn, g_attn);
    cudaGetSymbolAddress((void**)&p_y1,   g_y1);
    cudaGetSymbolAddress((void**)&p_lny1, g_lny1);
    cudaGetSymbolAddress((void**)&p_h,    g_h);

    // LN1 on y
    ln_reduce1<<<dim3(256, BB), 256>>>(y);
    ln_reduce2<<<BB, 256>>>();
    ln_apply<<<dim3(256, BB), 256>>>(y, ln1w, ln1b, p_lny);

    // Q = x@Wq+bq ; K = lny@Wk+bk ; V = lny@Wv+bv
    tgemm<0><<<dim3(DD/128, MM/128), 256>>>(x,     Wq, bq, nullptr, p_q, DD, DD);
    tgemm<0><<<dim3(DD/128, MM/128), 256>>>(p_lny, Wk, bk, nullptr, p_k, DD, DD);
    tgemm<0><<<dim3(DD/128, MM/128), 256>>>(p_lny, Wv, bv, nullptr, p_v, DD, DD);

    // suffix sums of V, then attention
    vsuffix_kernel<<<BB*HH, 1024>>>();
    attn_kernel<<<dim3(LL/RPB, HH, BB), 512>>>(p_attn);

    // y1 = y + attn@Wo + bo
    tgemm<2><<<dim3(DD/128, MM/128), 256>>>(p_attn, Wo, bo, y, p_y1, DD, DD);

    // LN2 on y1
    ln_reduce1<<<dim3(256, BB), 256>>>(p_y1);
    ln_reduce2<<<BB, 256>>>();
    ln_apply<<<dim3(256, BB), 256>>>(p_y1, ln2w, ln2b, p_lny1);

    // h = relu(lny1@W1 + b1) ; out = y1 + h@W2 + b2
    tgemm<1><<<dim3(DFF/128, MM/128), 256>>>(p_lny1, W1, b1, nullptr, p_h, DFF, DD);
    tgemm<2><<<dim3(DD/128,  MM/128), 256>>>(p_h,    W2, b2, p_y1,    out, DD, DFF);
}

// round 4
// speedup vs baseline: 4.3139x; 2.2617x over previous
#include <cuda_runtime.h>
#include <cuda_bf16.h>
#include <math.h>
#include <stdint.h>

#define BB 2
#define LL 2048
#define DD 1024
#define HH 16
#define DKK 64
#define DFF 4096
#define MM (BB*LL)   // 4096
#define EPS 1e-5f

// ================= helpers =================
__device__ __forceinline__ uint32_t smem_u32(const void* p) {
    uint32_t a;
    asm("{ .reg .u64 t; cvta.to.shared.u64 t, %1; cvt.u32.u64 %0, t; }" : "=r"(a) : "l"(p));
    return a;
}

#define LDSM_X4(r, addr) \
    asm volatile("ldmatrix.sync.aligned.m8n8.x4.shared.b16 {%0,%1,%2,%3}, [%4];" \
        : "=r"((r)[0]), "=r"((r)[1]), "=r"((r)[2]), "=r"((r)[3]) : "r"(addr))
#define LDSM_X4T(r, addr) \
    asm volatile("ldmatrix.sync.aligned.m8n8.x4.trans.shared.b16 {%0,%1,%2,%3}, [%4];" \
        : "=r"((r)[0]), "=r"((r)[1]), "=r"((r)[2]), "=r"((r)[3]) : "r"(addr))

#define MMA16816(d, a, b0, b1) \
    asm volatile("mma.sync.aligned.m16n8k16.row.col.f32.bf16.bf16.f32 " \
        "{%0,%1,%2,%3}, {%4,%5,%6,%7}, {%8,%9}, {%0,%1,%2,%3};" \
        : "+f"((d)[0]), "+f"((d)[1]), "+f"((d)[2]), "+f"((d)[3]) \
        : "r"((a)[0]), "r"((a)[1]), "r"((a)[2]), "r"((a)[3]), "r"(b0), "r"(b1))

#define STS128U(addr, a, b, c, d) \
    asm volatile("st.shared.v4.b32 [%0], {%1, %2, %3, %4};" \
                 :: "r"((uint32_t)(addr)), "r"(a), "r"(b), "r"(c), "r"(d) : "memory")
#define STS64U(addr, a, b) \
    asm volatile("st.shared.v2.b32 [%0], {%1, %2};" \
                 :: "r"((uint32_t)(addr)), "r"(a), "r"(b) : "memory")

// exact split: x = hi + lo, hi = truncate-to-bf16(x); pack pairs (x0 -> low half)
__device__ __forceinline__ void split2(float x0, float x1, uint32_t& hi, uint32_t& lo) {
    uint32_t u0 = __float_as_uint(x0) & 0xffff0000u;
    uint32_t u1 = __float_as_uint(x1) & 0xffff0000u;
    hi = (u0 >> 16) | u1;
    float l0 = x0 - __uint_as_float(u0);
    float l1 = x1 - __uint_as_float(u1);
    __nv_bfloat162 p = __float22bfloat162_rn(make_float2(l0, l1));
    lo = *reinterpret_cast<uint32_t*>(&p);
}
__device__ __forceinline__ uint32_t packbf(float x0, float x1) {
    __nv_bfloat162 p = __float22bfloat162_rn(make_float2(x0, x1));
    return *reinterpret_cast<uint32_t*>(&p);
}

// ================= scratch =================
__device__ float g_lny [BB*LL*DD];
__device__ float g_q   [BB*LL*DD];
__device__ float g_k   [BB*LL*DD];
__device__ float g_v   [BB*LL*DD];
__device__ float g_vsuf[BB*HH*LL*DKK];
__device__ float g_attn[BB*LL*DD];
__device__ float g_y1  [BB*LL*DD];
__device__ float g_lny1[BB*LL*DD];
__device__ float g_h   [BB*LL*DFF];
__device__ float g_part[BB*256*2];
__device__ float g_stats[BB*2];

// ================= LayerNorm over (L,D) jointly =================
__global__ void ln_reduce1(const float* __restrict__ x) {
    const int batch = blockIdx.y;
    const int chunk = (LL*DD)/256;
    long base = (long)batch*LL*DD + (long)blockIdx.x*chunk;
    float s = 0.f, s2 = 0.f;
    for (int i = threadIdx.x; i < chunk; i += 256) {
        float v = x[base + i];
        s += v; s2 += v*v;
    }
    __shared__ float sh[256], sh2[256];
    sh[threadIdx.x] = s; sh2[threadIdx.x] = s2;
    __syncthreads();
    for (int o = 128; o > 0; o >>= 1) {
        if (threadIdx.x < o) { sh[threadIdx.x] += sh[threadIdx.x+o]; sh2[threadIdx.x] += sh2[threadIdx.x+o]; }
        __syncthreads();
    }
    if (threadIdx.x == 0) {
        g_part[(batch*256 + blockIdx.x)*2 + 0] = sh[0];
        g_part[(batch*256 + blockIdx.x)*2 + 1] = sh2[0];
    }
}

__global__ void ln_reduce2() {
    const int batch = blockIdx.x;
    __shared__ float sh[256], sh2[256];
    sh[threadIdx.x]  = g_part[(batch*256 + threadIdx.x)*2 + 0];
    sh2[threadIdx.x] = g_part[(batch*256 + threadIdx.x)*2 + 1];
    __syncthreads();
    for (int o = 128; o > 0; o >>= 1) {
        if (threadIdx.x < o) { sh[threadIdx.x] += sh[threadIdx.x+o]; sh2[threadIdx.x] += sh2[threadIdx.x+o]; }
        __syncthreads();
    }
    if (threadIdx.x == 0) {
        const float inv = 1.0f / (float)(LL*DD);
        float mu  = sh[0]  * inv;
        float var = sh2[0] * inv - mu*mu;
        g_stats[batch*2 + 0] = mu;
        g_stats[batch*2 + 1] = rsqrtf(var + EPS);
    }
}

__global__ void ln_apply(const float* __restrict__ x, const float* __restrict__ w,
                         const float* __restrict__ b, float* __restrict__ out) {
    const int batch = blockIdx.y;
    const float mu   = g_stats[batch*2 + 0];
    const float rstd = g_stats[batch*2 + 1];
    const long base = (long)batch*LL*DD;
    for (long i = (long)blockIdx.x*blockDim.x + threadIdx.x; i < (long)LL*DD; i += (long)gridDim.x*blockDim.x) {
        out[base + i] = (x[base + i] - mu) * rstd * w[i] + b[i];
    }
}

// ================= bf16x3 mma.sync GEMM (unchanged from R3) =================
#define ASTR 48
#define BSTR 272
#define OFF_ALO 6144
#define OFF_BHI 12288
#define OFF_BLO 16640
#define STAGE   20992

template<int EPI>
__global__ void __launch_bounds__(256)
tgemm(const float* __restrict__ A, const float* __restrict__ W,
      const float* __restrict__ bias, const float* __restrict__ R,
      float* __restrict__ C, int N, int K)
{
    __shared__ __align__(128) char sm[2*STAGE];
    const uint32_t sbase = smem_u32(sm);

    const int t = threadIdx.x;
    const int lane = t & 31, wid = t >> 5;
    const int g = lane >> 2, tig = lane & 3;
    const int wm = wid >> 2, wn = wid & 3;
    const int bm = blockIdx.y * 128, bn = blockIdx.x * 128;

    const int ar = t >> 1, aq = t & 1;
    const int br = t >> 4, bc = (t & 15) * 8;

    const float* Agp = A + (size_t)(bm + ar) * K + aq * 8;
    const float* Bgp = W + (size_t)br * N + bn + bc;

    const uint32_t a_base = sbase + (uint32_t)(wm*64 + (lane & 15)) * ASTR + ((lane >> 4) & 1) * 16;
    const uint32_t b_base = sbase + OFF_BHI + (uint32_t)(lane & 15) * BSTR + (uint32_t)wn * 64 + ((lane >> 4) & 1) * 16;

    float acc[4][4][4];
    #pragma unroll
    for (int i = 0; i < 4; i++)
        #pragma unroll
        for (int j = 0; j < 4; j++)
            #pragma unroll
            for (int c = 0; c < 4; c++) acc[i][j][c] = 0.f;

    const int nk = K / 16;

    float4 av0, av1, bv0, bv1;
    av0 = *(const float4*)(Agp);
    av1 = *(const float4*)(Agp + 4);
    bv0 = *(const float4*)(Bgp);
    bv1 = *(const float4*)(Bgp + 4);

    auto store_stage = [&](int buf) {
        const uint32_t sb = sbase + (uint32_t)buf * STAGE;
        uint32_t h0,l0,h1,l1,h2,l2,h3,l3;
        split2(av0.x, av0.y, h0, l0);
        split2(av0.z, av0.w, h1, l1);
        split2(av1.x, av1.y, h2, l2);
        split2(av1.z, av1.w, h3, l3);
        uint32_t aaddr = sb + (uint32_t)ar * ASTR + (uint32_t)aq * 16;
        STS128U(aaddr, h0, h1, h2, h3);
        STS128U(aaddr + OFF_ALO, l0, l1, l2, l3);
        split2(bv0.x, bv0.y, h0, l0);
        split2(bv0.z, bv0.w, h1, l1);
        split2(bv1.x, bv1.y, h2, l2);
        split2(bv1.z, bv1.w, h3, l3);
        uint32_t baddr = sb + OFF_BHI + (uint32_t)br * BSTR + (uint32_t)bc * 2;
        STS128U(baddr, h0, h1, h2, h3);
        STS128U(baddr + (OFF_BLO - OFF_BHI), l0, l1, l2, l3);
    };

    store_stage(0);
    __syncthreads();

    for (int s = 0; s < nk; s++) {
        const int buf = s & 1;
        if (s + 1 < nk) {
            const int k0 = (s + 1) * 16;
            av0 = *(const float4*)(Agp + k0);
            av1 = *(const float4*)(Agp + k0 + 4);
            bv0 = *(const float4*)(Bgp + (size_t)k0 * N);
            bv1 = *(const float4*)(Bgp + (size_t)k0 * N + 4);
        }

        const uint32_t so = (uint32_t)buf * STAGE;
        uint32_t ah[4][4], bhf[2][4];
        #pragma unroll
        for (int i = 0; i < 4; i++) LDSM_X4(ah[i], a_base + so + i * (16*ASTR));
        #pragma unroll
        for (int j2 = 0; j2 < 2; j2++) LDSM_X4T(bhf[j2], b_base + so + j2 * 32);

        #pragma unroll
        for (int i = 0; i < 4; i++)
            #pragma unroll
            for (int j = 0; j < 4; j++)
                MMA16816(acc[i][j], ah[i], bhf[j>>1][(j&1)*2], bhf[j>>1][(j&1)*2+1]);

        {
            uint32_t blf[2][4];
            #pragma unroll
            for (int j2 = 0; j2 < 2; j2++) LDSM_X4T(blf[j2], b_base + so + (OFF_BLO - OFF_BHI) + j2 * 32);
            #pragma unroll
            for (int i = 0; i < 4; i++)
                #pragma unroll
                for (int j = 0; j < 4; j++)
                    MMA16816(acc[i][j], ah[i], blf[j>>1][(j&1)*2], blf[j>>1][(j&1)*2+1]);
        }
        {
            uint32_t alf[4][4];
            #pragma unroll
            for (int i = 0; i < 4; i++) LDSM_X4(alf[i], a_base + so + OFF_ALO + i * (16*ASTR));
            #pragma unroll
            for (int i = 0; i < 4; i++)
                #pragma unroll
                for (int j = 0; j < 4; j++)
                    MMA16816(acc[i][j], alf[i], bhf[j>>1][(j&1)*2], bhf[j>>1][(j&1)*2+1]);
        }

        if (s + 1 < nk) store_stage(buf ^ 1);
        __syncthreads();
    }

    #pragma unroll
    for (int i = 0; i < 4; i++) {
        const int row0 = bm + wm*64 + i*16 + g;
        #pragma unroll
        for (int j = 0; j < 4; j++) {
            const int col0 = bn + wn*32 + j*8 + 2*tig;
            float2 bs = *(const float2*)(bias + col0);
            float2 c01 = make_float2(acc[i][j][0] + bs.x, acc[i][j][1] + bs.y);
            float2 c23 = make_float2(acc[i][j][2] + bs.x, acc[i][j][3] + bs.y);
            if (EPI == 1) {
                c01.x = fmaxf(c01.x, 0.f); c01.y = fmaxf(c01.y, 0.f);
                c23.x = fmaxf(c23.x, 0.f); c23.y = fmaxf(c23.y, 0.f);
            }
            if (EPI == 2) {
                float2 r0 = *(const float2*)(R + (size_t)row0 * N + col0);
                float2 r1 = *(const float2*)(R + (size_t)(row0+8) * N + col0);
                c01.x += r0.x; c01.y += r0.y;
                c23.x += r1.x; c23.y += r1.y;
            }
            *(float2*)(C + (size_t)row0 * N + col0)     = c01;
            *(float2*)(C + (size_t)(row0+8) * N + col0) = c23;
        }
    }
}

// ================= V suffix sums (segmented scan) =================
__global__ void __launch_bounds__(1024) vsuffix_kernel() {
    const int bh = blockIdx.x;
    const int b = bh / HH, h = bh % HH;
    const int d = threadIdx.x & 63;
    const int seg = threadIdx.x >> 6;
    const int SEGK = LL / 16;
    __shared__ float part[16][64];
    const size_t vbase = (size_t)b*LL*DD + (size_t)h*DKK + d;
    const int k0 = seg * SEGK;
    float s = 0.f;
    for (int k = k0; k < k0 + SEGK; k++) s += g_v[vbase + (size_t)k*DD];
    part[seg][d] = s;
    __syncthreads();
    float acc = 0.f;
    for (int ss = seg + 1; ss < 16; ss++) acc += part[ss][d];
    const size_t sb = (size_t)bh*LL*DKK + d;
    for (int k = k0 + SEGK - 1; k >= k0; k--) {
        g_vsuf[sb + (size_t)k*DKK] = acc;
        acc += g_v[vbase + (size_t)k*DD];
    }
}

// ================= tensor-core flash attention =================
// 64 q-rows x 64-key chunks, 4 warps (each 16 rows x 64 keys), m=0 fixed
// (scores tiny: no overflow), tril-to-zero tail analytic via g_vsuf.
// smem rows padded to 144B -> conflict-free ldmatrix.
#define TSTR 144
#define QTILE 9216

__global__ void __launch_bounds__(128)
fattn_kernel(float* __restrict__ out) {
    __shared__ __align__(16) char smr[5*QTILE];
    const uint32_t sQhi = smem_u32(smr);
    const uint32_t sQlo = sQhi + QTILE;
    const uint32_t sKhi = sQhi + 2*QTILE;
    const uint32_t sKlo = sQhi + 3*QTILE;
    const uint32_t sV   = sQhi + 4*QTILE;

    const int b = blockIdx.z, h = blockIdx.y;
    const int qt = gridDim.x - 1 - blockIdx.x;   // heavy tiles first
    const int q0 = qt * 64;
    const int t = threadIdx.x, w = t >> 5, lane = t & 31;
    const int g = lane >> 2, tg = lane & 3;

    const float SC = 0.125f * 1.4426950408889634f;  // 1/sqrt(64) * log2(e)

    // ---- load + split Q tile (scaled) ----
    {
        const int r = t >> 1, hf = t & 1;
        const float* qp = g_q + ((size_t)(b*LL + q0 + r))*DD + h*DKK + hf*32;
        const uint32_t dhi = sQhi + (uint32_t)r*TSTR + hf*64;
        const uint32_t dlo = sQlo + (uint32_t)r*TSTR + hf*64;
        #pragma unroll
        for (int j = 0; j < 8; j++) {
            float4 v = *(const float4*)(qp + j*4);
            v.x *= SC; v.y *= SC; v.z *= SC; v.w *= SC;
            uint32_t h0,l0,h1,l1;
            split2(v.x, v.y, h0, l0); split2(v.z, v.w, h1, l1);
            STS64U(dhi + j*8, h0, h1);
            STS64U(dlo + j*8, l0, l1);
        }
    }
    __syncthreads();

    // ---- preload Q A-fragments (4 k-chunks, hi+lo) ----
    uint32_t qh[4][4], qlo[4][4];
    {
        const int mi = lane >> 3, li = lane & 7;
        const uint32_t ro = (uint32_t)(w*16 + ((mi&1)<<3) + li) * TSTR + (uint32_t)((mi>>1)<<4);
        #pragma unroll
        for (int kc4 = 0; kc4 < 4; kc4++) {
            LDSM_X4(qh[kc4],  sQhi + ro + kc4*32);
            LDSM_X4(qlo[kc4], sQlo + ro + kc4*32);
        }
    }

    float oacc[8][4];
    #pragma unroll
    for (int f = 0; f < 8; f++)
        #pragma unroll
        for (int c = 0; c < 4; c++) oacc[f][c] = 0.f;
    float ls0 = 0.f, ls1 = 0.f;

    const int nch = qt + 1;
    const int mi = lane >> 3, li = lane & 7;

    for (int ci = 0; ci < nch; ci++) {
        const int kc = ci * 64;
        __syncthreads();
        // ---- load K (hi/lo) and V (bf16) chunk ----
        {
            const int r = t >> 1, hf = t & 1;
            const size_t gbase = ((size_t)(b*LL + kc + r))*DD + h*DKK + hf*32;
            const float* kp = g_k + gbase;
            const float* vp = g_v + gbase;
            const uint32_t dkh = sKhi + (uint32_t)r*TSTR + hf*64;
            const uint32_t dkl = sKlo + (uint32_t)r*TSTR + hf*64;
            const uint32_t dv  = sV   + (uint32_t)r*TSTR + hf*64;
            #pragma unroll
            for (int j = 0; j < 8; j++) {
                float4 kv = *(const float4*)(kp + j*4);
                uint32_t h0,l0,h1,l1;
                split2(kv.x, kv.y, h0, l0); split2(kv.z, kv.w, h1, l1);
                STS64U(dkh + j*8, h0, h1);
                STS64U(dkl + j*8, l0, l1);
                float4 vv = *(const float4*)(vp + j*4);
                STS64U(dv + j*8, packbf(vv.x, vv.y), packbf(vv.z, vv.w));
            }
        }
        __syncthreads();

        // ---- S = Q K^T (3-pass hi/lo) ----
        float sacc[8][4];
        #pragma unroll
        for (int f = 0; f < 8; f++)
            #pragma unroll
            for (int c = 0; c < 4; c++) sacc[f][c] = 0.f;

        #pragma unroll
        for (int kc4 = 0; kc4 < 4; kc4++) {
            uint32_t bk[8][2];
            // Khi fragments: 4x ldsm.x4, each covers 2 key-groups x k16
            #pragma unroll
            for (int j2 = 0; j2 < 4; j2++) {
                uint32_t tmp[4];
                const uint32_t ro = (uint32_t)((2*j2 + (mi>>1))*8 + li) * TSTR
                                  + (uint32_t)(kc4*32 + (mi&1)*16);
                LDSM_X4(tmp, sKhi + ro);
                bk[2*j2][0] = tmp[0]; bk[2*j2][1] = tmp[1];
                bk[2*j2+1][0] = tmp[2]; bk[2*j2+1][1] = tmp[3];
            }
            #pragma unroll
            for (int f = 0; f < 8; f++) MMA16816(sacc[f], qh[kc4], bk[f][0], bk[f][1]);
            #pragma unroll
            for (int f = 0; f < 8; f++) MMA16816(sacc[f], qlo[kc4], bk[f][0], bk[f][1]);
            // Klo fragments (reuse regs)
            #pragma unroll
            for (int j2 = 0; j2 < 4; j2++) {
                uint32_t tmp[4];
                const uint32_t ro = (uint32_t)((2*j2 + (mi>>1))*8 + li) * TSTR
                                  + (uint32_t)(kc4*32 + (mi&1)*16);
                LDSM_X4(tmp, sKlo + ro);
                bk[2*j2][0] = tmp[0]; bk[2*j2][1] = tmp[1];
                bk[2*j2+1][0] = tmp[2]; bk[2*j2+1][1] = tmp[3];
            }
            #pragma unroll
            for (int f = 0; f < 8; f++) MMA16816(sacc[f], qh[kc4], bk[f][0], bk[f][1]);
        }

        // ---- P = exp2(S) with causal zero-mask on diagonal chunk ----
        const int row0 = q0 + w*16 + g;
        if (ci == nch - 1) {
            #pragma unroll
            for (int f = 0; f < 8; f++) {
                const int col = kc + f*8 + 2*tg;
                sacc[f][0] = (col   <= row0)   ? exp2f(sacc[f][0]) : 0.f;
                sacc[f][1] = (col+1 <= row0)   ? exp2f(sacc[f][1]) : 0.f;
                sacc[f][2] = (col   <= row0+8) ? exp2f(sacc[f][2]) : 0.f;
                sacc[f][3] = (col+1 <= row0+8) ? exp2f(sacc[f][3]) : 0.f;
            }
        } else {
            #pragma unroll
            for (int f = 0; f < 8; f++) {
                sacc[f][0] = exp2f(sacc[f][0]);
                sacc[f][1] = exp2f(sacc[f][1]);
                sacc[f][2] = exp2f(sacc[f][2]);
                sacc[f][3] = exp2f(sacc[f][3]);
            }
        }
        #pragma unroll
        for (int f = 0; f < 8; f++) {
            ls0 += sacc[f][0] + sacc[f][1];
            ls1 += sacc[f][2] + sacc[f][3];
        }

        // ---- O += P V ----
        #pragma unroll
        for (int kc4 = 0; kc4 < 4; kc4++) {
            uint32_t aP[4];
            aP[0] = packbf(sacc[2*kc4][0],   sacc[2*kc4][1]);
            aP[1] = packbf(sacc[2*kc4][2],   sacc[2*kc4][3]);
            aP[2] = packbf(sacc[2*kc4+1][0], sacc[2*kc4+1][1]);
            aP[3] = packbf(sacc[2*kc4+1][2], sacc[2*kc4+1][3]);
            uint32_t bv[8][2];
            #pragma unroll
            for (int j2 = 0; j2 < 4; j2++) {
                uint32_t tmp[4];
                const uint32_t ro = (uint32_t)(kc4*16 + (mi&1)*8 + li) * TSTR
                                  + (uint32_t)((2*j2 + (mi>>1))*16);
                LDSM_X4T(tmp, sV + ro);
                bv[2*j2][0] = tmp[0]; bv[2*j2][1] = tmp[1];
                bv[2*j2+1][0] = tmp[2]; bv[2*j2+1][1] = tmp[3];
            }
            #pragma unroll
            for (int f = 0; f < 8; f++) MMA16816(oacc[f], aP, bv[f][0], bv[f][1]);
        }
    }

    // ---- reduce row sums across the 4 lanes sharing a row ----
    ls0 += __shfl_xor_sync(0xffffffffu, ls0, 1);
    ls0 += __shfl_xor_sync(0xffffffffu, ls0, 2);
    ls1 += __shfl_xor_sync(0xffffffffu, ls1, 1);
    ls1 += __shfl_xor_sync(0xffffffffu, ls1, 2);

    const int row0 = q0 + w*16 + g;
    const int row1 = row0 + 8;
    const float inv0 = 1.0f / (ls0 + (float)(LL - 1 - row0));
    const float inv1 = 1.0f / (ls1 + (float)(LL - 1 - row1));

    const size_t vs0 = ((size_t)((b*HH + h)*LL) + row0) * DKK;
    const size_t vs1 = ((size_t)((b*HH + h)*LL) + row1) * DKK;
    float* o0 = out + ((size_t)(b*LL + row0))*DD + h*DKK;
    float* o1 = out + ((size_t)(b*LL + row1))*DD + h*DKK;
    #pragma unroll
    for (int f = 0; f < 8; f++) {
        const int col = f*8 + 2*tg;
        float2 t0 = *(const float2*)(g_vsuf + vs0 + col);
        float2 t1 = *(const float2*)(g_vsuf + vs1 + col);
        float2 r0 = make_float2((oacc[f][0] + t0.x) * inv0, (oacc[f][1] + t0.y) * inv0);
        float2 r1 = make_float2((oacc[f][2] + t1.x) * inv1, (oacc[f][3] + t1.y) * inv1);
        *(float2*)(o0 + col) = r0;
        *(float2*)(o1 + col) = r1;
    }
}

// ================= launch =================
extern "C" void kernel_launch(void* const* d_in, const int* in_sizes, int n_in,
                              void* d_out, int out_size) {
    const float* x    = (const float*)d_in[0];
    const float* y    = (const float*)d_in[1];
    const float* Wq   = (const float*)d_in[2];
    const float* bq   = (const float*)d_in[3];
    const float* Wk   = (const float*)d_in[4];
    const float* bk   = (const float*)d_in[5];
    const float* Wv   = (const float*)d_in[6];
    const float* bv   = (const float*)d_in[7];
    const float* Wo   = (const float*)d_in[8];
    const float* bo   = (const float*)d_in[9];
    const float* W1   = (const float*)d_in[10];
    const float* b1   = (const float*)d_in[11];
    const float* W2   = (const float*)d_in[12];
    const float* b2   = (const float*)d_in[13];
    const float* ln1w = (const float*)d_in[14];
    const float* ln1b = (const float*)d_in[15];
    const float* ln2w = (const float*)d_in[16];
    const float* ln2b = (const float*)d_in[17];
    float* out = (float*)d_out;

    float *p_lny, *p_q, *p_k, *p_v, *p_attn, *p_y1, *p_lny1, *p_h;
    cudaGetSymbolAddress((void**)&p_lny,  g_lny);
    cudaGetSymbolAddress((void**)&p_q,    g_q);
    cudaGetSymbolAddress((void**)&p_k,    g_k);
    cudaGetSymbolAddress((void**)&p_v,    g_v);
    cudaGetSymbolAddress((void**)&p_attn, g_attn);
    cudaGetSymbolAddress((void**)&p_y1,   g_y1);
    cudaGetSymbolAddress((void**)&p_lny1, g_lny1);
    cudaGetSymbolAddress((void**)&p_h,    g_h);

    // LN1 on y
    ln_reduce1<<<dim3(256, BB), 256>>>(y);
    ln_reduce2<<<BB, 256>>>();
    ln_apply<<<dim3(256, BB), 256>>>(y, ln1w, ln1b, p_lny);

    // Q = x@Wq+bq ; K = lny@Wk+bk ; V = lny@Wv+bv
    tgemm<0><<<dim3(DD/128, MM/128), 256>>>(x,     Wq, bq, nullptr, p_q, DD, DD);
    tgemm<0><<<dim3(DD/128, MM/128), 256>>>(p_lny, Wk, bk, nullptr, p_k, DD, DD);
    tgemm<0><<<dim3(DD/128, MM/128), 256>>>(p_lny, Wv, bv, nullptr, p_v, DD, DD);

    // suffix sums of V, then attention
    vsuffix_kernel<<<BB*HH, 1024>>>();
    fattn_kernel<<<dim3(LL/64, HH, BB), 128>>>(p_attn);

    // y1 = y + attn@Wo + bo
    tgemm<2><<<dim3(DD/128, MM/128), 256>>>(p_attn, Wo, bo, y, p_y1, DD, DD);

    // LN2 on y1
    ln_reduce1<<<dim3(256, BB), 256>>>(p_y1);
    ln_reduce2<<<BB, 256>>>();
    ln_apply<<<dim3(256, BB), 256>>>(p_y1, ln2w, ln2b, p_lny1);

    // h = relu(lny1@W1 + b1) ; out = y1 + h@W2 + b2
    tgemm<1><<<dim3(DFF/128, MM/128), 256>>>(p_lny1, W1, b1, nullptr, p_h, DFF, DD);
    tgemm<2><<<dim3(DD/128,  MM/128), 256>>>(p_h,    W2, b2, p_y1,    out, DD, DFF);
}